// round 15
// baseline (speedup 1.0000x reference)
#include <cuda_runtime.h>
#include <cuda_fp16.h>
#include <math.h>
#include <stdint.h>

#define H 1024
#define M 3584
#define E 8
#define T 2048
#define A_MAX (T * 2)
#define A_PAD (A_MAX + 128)   // GEMM2 A-loader reads full 128-row tiles unguarded

// ---------------------------------------------------------------------------
// scratch (device globals; allocation forbidden)
// ---------------------------------------------------------------------------
__device__ int   g_expert_count[E];
__device__ int   g_expert_offset[E];
__device__ int   g_assign_token[A_MAX];
__device__ float g_assign_w[A_MAX];
__device__ int   g_top_i[A_MAX];
__device__ float g_top_w[A_MAX];
__device__ int   g_pos_of[A_MAX];            // assignment (t*2+j) -> grouped pos

__device__ __align__(16) __half g_xh [(size_t)T * H];
__device__ __align__(16) __half g_wg [(size_t)E * H * M];   // [e][h][m] fp16
__device__ __align__(16) __half g_wu [(size_t)E * H * M];
__device__ __align__(16) __half g_wd [(size_t)E * M * H];
__device__ __align__(16) __half g_hid[(size_t)A_PAD * M];   // [pos][m], padded
__device__ __align__(16) float  g_part[(size_t)A_MAX * H];  // weighted partials

// ---------------------------------------------------------------------------
// helpers
// ---------------------------------------------------------------------------
__device__ __forceinline__ uint32_t smem_u32(const void* p) {
    uint32_t a;
    asm("{ .reg .u64 t; cvta.to.shared.u64 t, %1; cvt.u32.u64 %0, t; }" : "=r"(a) : "l"(p));
    return a;
}
#define SWZ(x) ((x) ^ (((x) >> 3) & 0x70))

#define CP16(dst, src) \
    asm volatile("cp.async.cg.shared.global [%0], [%1], 16;" \
                 :: "r"(dst), "l"(__cvta_generic_to_global(src)) : "memory")
#define CP16Z(dst, src, sz) \
    asm volatile("cp.async.cg.shared.global [%0], [%1], 16, %2;" \
                 :: "r"(dst), "l"(__cvta_generic_to_global(src)), "r"(sz) : "memory")
#define CP_COMMIT() asm volatile("cp.async.commit_group;" ::: "memory")
#define CP_WAIT(n)  asm volatile("cp.async.wait_group %0;" :: "n"(n) : "memory")

#define LDSM4(r, addr) \
    asm volatile("ldmatrix.sync.aligned.m8n8.x4.shared.b16 {%0,%1,%2,%3}, [%4];" \
        : "=r"((r)[0]), "=r"((r)[1]), "=r"((r)[2]), "=r"((r)[3]) : "r"(addr))
#define LDSM2T(r, addr) \
    asm volatile("ldmatrix.sync.aligned.m8n8.x2.trans.shared.b16 {%0,%1}, [%2];" \
        : "=r"((r)[0]), "=r"((r)[1]) : "r"(addr))

#define MMA16816(c, a, b) \
    asm volatile("mma.sync.aligned.m16n8k16.row.col.f32.f16.f16.f32 " \
        "{%0,%1,%2,%3}, {%4,%5,%6,%7}, {%8,%9}, {%0,%1,%2,%3};" \
        : "+f"((c)[0]), "+f"((c)[1]), "+f"((c)[2]), "+f"((c)[3]) \
        : "r"((a)[0]), "r"((a)[1]), "r"((a)[2]), "r"((a)[3]), "r"((b)[0]), "r"((b)[1]))

__device__ __forceinline__ uint32_t pack2h(float v0, float v1) {
    __half2 h = __floats2half2_rn(v0, v1);
    return *(uint32_t*)&h;
}

// ---------------------------------------------------------------------------
// mma core: one 64-wide K chunk, warp tile 64 rows x 32 cols (validated)
// ---------------------------------------------------------------------------
__device__ __forceinline__ void mma_chunk(float acc[4][4][4],
                                          uint32_t aP, uint32_t bP,
                                          int m0w, int n0w, int lane)
{
    const int lr = lane & 15;
    const int lc = (lane >> 4) << 3;
    const int kr = (lane & 7) + (((lane >> 3) & 1) << 3);
#pragma unroll
    for (int ks = 0; ks < 4; ks++) {
        const int k0 = ks * 16;
        uint32_t bf[4][2];
#pragma unroll
        for (int nf = 0; nf < 4; nf++) {
            int nl = n0w + nf * 8;
            uint32_t boff = SWZ((uint32_t)((k0 + kr) * 128 + nl * 2));
            LDSM2T(bf[nf], bP + boff);
        }
#pragma unroll
        for (int mf = 0; mf < 4; mf++) {
            uint32_t aoff = SWZ((uint32_t)((m0w + mf * 16 + lr) * 128 + (k0 + lc) * 2));
            uint32_t af[4];
            LDSM4(af, aP + aoff);
#pragma unroll
            for (int nf = 0; nf < 4; nf++)
                MMA16816(acc[mf][nf], af, bf[nf]);
        }
    }
}

// ---------------------------------------------------------------------------
// conversions: ONE launch for all three weights + xconv
// ---------------------------------------------------------------------------
__global__ void __launch_bounds__(256) convw_kernel(const float* __restrict__ wg,
                                                    const float* __restrict__ wu,
                                                    const float* __restrict__ wd) {
    const size_t SEG = (size_t)E * M * H / 4;
    size_t i = (size_t)blockIdx.x * 256 + threadIdx.x;
    const float* in;
    __half* outp;
    if (i < SEG)          { in = wg; outp = g_wg; }
    else if (i < 2 * SEG) { in = wu; outp = g_wu; i -= SEG; }
    else                  { in = wd; outp = g_wd; i -= 2 * SEG; }
    float4 v = ((const float4*)in)[i];
    ((uint2*)outp)[i] = make_uint2(pack2h(v.x, v.y), pack2h(v.z, v.w));
}

__global__ void __launch_bounds__(256) xconv_kernel(const float* __restrict__ x) {
    size_t i = (size_t)blockIdx.x * 256 + threadIdx.x;   // over T*H/4
    float4 v = ((const float4*)x)[i];
    ((uint2*)g_xh)[i] = make_uint2(pack2h(v.x, v.y), pack2h(v.z, v.w));
}

// ---------------------------------------------------------------------------
// router: warp-per-token (8 tokens per 256-thread block)
// ---------------------------------------------------------------------------
__global__ void __launch_bounds__(256) router_kernel(
    const float* __restrict__ x, const float* __restrict__ gw,
    float* __restrict__ logits_out)
{
    const int wid = threadIdx.x >> 5, lane = threadIdx.x & 31;
    const int t = blockIdx.x * 8 + wid;
    const float* xr = x + (size_t)t * H;

    float acc[E];
#pragma unroll
    for (int e = 0; e < E; e++) acc[e] = 0.f;
#pragma unroll 4
    for (int j = 0; j < H / 32; j++) {
        int h = j * 32 + lane;
        float xv = xr[h];
        float4 a = *(const float4*)(gw + (size_t)h * E);
        float4 b = *(const float4*)(gw + (size_t)h * E + 4);
        acc[0] += xv * a.x; acc[1] += xv * a.y;
        acc[2] += xv * a.z; acc[3] += xv * a.w;
        acc[4] += xv * b.x; acc[5] += xv * b.y;
        acc[6] += xv * b.z; acc[7] += xv * b.w;
    }
#pragma unroll
    for (int s = 16; s > 0; s >>= 1)
#pragma unroll
        for (int e = 0; e < E; e++)
            acc[e] += __shfl_down_sync(0xffffffffu, acc[e], s);

    if (lane == 0) {
        float l[E];
#pragma unroll
        for (int e = 0; e < E; e++) {
            l[e] = acc[e];
            if (logits_out) logits_out[(size_t)t * E + e] = l[e];
        }
        float mx = l[0];
#pragma unroll
        for (int e = 1; e < E; e++) mx = fmaxf(mx, l[e]);
        float p[E];
#pragma unroll
        for (int e = 0; e < E; e++) p[e] = expf(l[e] - mx);
        int i0 = 0;
#pragma unroll
        for (int e = 1; e < E; e++) if (p[e] > p[i0]) i0 = e;
        int i1 = (i0 == 0) ? 1 : 0;
#pragma unroll
        for (int e = 0; e < E; e++) if (e != i0 && p[e] > p[i1]) i1 = e;
        float s2 = p[i0] + p[i1];
        g_top_i[t * 2 + 0] = i0; g_top_w[t * 2 + 0] = p[i0] / s2;
        g_top_i[t * 2 + 1] = i1; g_top_w[t * 2 + 1] = p[i1] / s2;
    }
}

__global__ void __launch_bounds__(256) build_assign_kernel() {
    __shared__ int cnt[E], cur[E];
    const int tid = threadIdx.x;
    if (tid < E) cnt[tid] = 0;
    __syncthreads();
    for (int a = tid; a < A_MAX; a += 256) atomicAdd(&cnt[g_top_i[a]], 1);
    __syncthreads();
    if (tid == 0) {
        int o = 0;
        for (int e = 0; e < E; e++) {
            g_expert_count[e] = cnt[e];
            g_expert_offset[e] = o;
            cur[e] = o;
            o += cnt[e];
        }
    }
    __syncthreads();
    for (int a = tid; a < A_MAX; a += 256) {
        int e = g_top_i[a];
        int pos = atomicAdd(&cur[e], 1);
        g_assign_token[pos] = a >> 1;
        g_assign_w[pos]     = g_top_w[a];
        g_pos_of[a]         = pos;
    }
}

// ---------------------------------------------------------------------------
// GEMM1 (R12-exact): hidden = silu(X*Wg) * (X*Wu)
// 128 gathered rows x 64 cols; warps 0-3 gate, 4-7 up; 2-stage cp.async
// stage (32KB): A 0..16K | BG 16K..24K | BU 24K..32K
// ---------------------------------------------------------------------------
#define G1_STAGE 32768
#define G1_BG 16384
#define G1_BU 24576
#define G1_SROW (2 * G1_STAGE)
#define G1_SMEM (2 * G1_STAGE + 512)

__device__ __forceinline__ void g1_load(uint32_t stg, int e, int n0, int kg,
                                        const int* srow, int tid) {
#pragma unroll
    for (int it = 0; it < 4; it++) {          // A: 128 rows x 128B
        int idx = tid + it * 256;
        int r = idx >> 3, q = idx & 7;
        int tok = srow[r];
        uint32_t sz = (tok >= 0) ? 16u : 0u;
        int tk = (tok >= 0) ? tok : 0;
        uint32_t o = SWZ((uint32_t)(r * 128 + q * 16));
        CP16Z(stg + o, g_xh + (size_t)tk * H + kg + q * 8, sz);
    }
#pragma unroll
    for (int it = 0; it < 2; it++) {          // Bg, Bu: rows = k (h), cols = n (m)
        int idx = tid + it * 256;
        int r = idx >> 3, q = idx & 7;
        size_t go = ((size_t)e * H + kg + r) * M + n0 + q * 8;
        uint32_t o = SWZ((uint32_t)(r * 128 + q * 16));
        CP16(stg + G1_BG + o, g_wg + go);
        CP16(stg + G1_BU + o, g_wu + go);
    }
}

__global__ void __launch_bounds__(256, 2) gemm1_mma() {
    const int e   = blockIdx.z;
    const int cnt = g_expert_count[e];
    const int t0  = blockIdx.x * 128;
    if (t0 >= cnt) return;
    const int off = g_expert_offset[e];
    const int n0  = blockIdx.y * 64;

    extern __shared__ __align__(1024) char smem[];
    const uint32_t sb = smem_u32(smem);
    int* srow = (int*)(smem + G1_SROW);
    const int tid = threadIdx.x, wid = tid >> 5, lane = tid & 31;

    if (tid < 128)
        srow[tid] = (t0 + tid < cnt) ? g_assign_token[off + t0 + tid] : -1;
    __syncthreads();

    const int gwp    = wid & 3;
    const int warp_m = gwp >> 1, warp_n = gwp & 1;
    const bool isUp  = wid >= 4;

    float acc[4][4][4];
#pragma unroll
    for (int a = 0; a < 4; a++)
#pragma unroll
        for (int b = 0; b < 4; b++)
#pragma unroll
            for (int c = 0; c < 4; c++) acc[a][b][c] = 0.f;

    const uint32_t bOff = isUp ? G1_BU : G1_BG;

    const int NCH = H / 64;   // 16
    g1_load(sb, e, n0, 0, srow, tid);
    CP_COMMIT();
    for (int ch = 0; ch < NCH; ch++) {
        const uint32_t cur = sb + (uint32_t)(ch & 1) * G1_STAGE;
        if (ch + 1 < NCH) {
            g1_load(sb + (uint32_t)((ch + 1) & 1) * G1_STAGE, e, n0, (ch + 1) * 64, srow, tid);
            CP_COMMIT();
            CP_WAIT(1);
        } else {
            CP_WAIT(0);
        }
        __syncthreads();
        mma_chunk(acc, cur, cur + bOff, warp_m * 64, warp_n * 32, lane);
        __syncthreads();
    }

    // epilogue: exchange up accums via smem, gate warps compute + store fp16
    float* smemU = (float*)smem;   // [128][65] fp32 overlay
    if (isUp) {
#pragma unroll
        for (int mf = 0; mf < 4; mf++)
#pragma unroll
            for (int nf = 0; nf < 4; nf++)
#pragma unroll
                for (int i = 0; i < 4; i++) {
                    int r = warp_m * 64 + mf * 16 + (lane >> 2) + ((i >> 1) << 3);
                    int c = warp_n * 32 + nf * 8 + 2 * (lane & 3) + (i & 1);
                    smemU[r * 65 + c] = acc[mf][nf][i];
                }
    }
    __syncthreads();
    if (!isUp) {
#pragma unroll
        for (int mf = 0; mf < 4; mf++)
#pragma unroll
            for (int nf = 0; nf < 4; nf++) {
                int rb = warp_m * 64 + mf * 16 + (lane >> 2);
                int cb = warp_n * 32 + nf * 8 + 2 * (lane & 3);
#pragma unroll
                for (int hf = 0; hf < 2; hf++) {
                    int r = rb + hf * 8;
                    if (t0 + r < cnt) {
                        float g0 = acc[mf][nf][hf * 2 + 0];
                        float g1 = acc[mf][nf][hf * 2 + 1];
                        float u0 = smemU[r * 65 + cb];
                        float u1 = smemU[r * 65 + cb + 1];
                        float h0 = (g0 / (1.f + __expf(-g0))) * u0;
                        float h1 = (g1 / (1.f + __expf(-g1))) * u1;
                        *(uint32_t*)(g_hid + (size_t)(off + t0 + r) * M + n0 + cb)
                            = pack2h(h0, h1);
                    }
                }
            }
    }
}

// ---------------------------------------------------------------------------
// GEMM2 (R12-exact): part[pos] = w * (hidden * Wd)
// 128 rows x 128 H-cols; 8 warps (2m x 4n); 2-stage cp.async
// stage (32KB): A 0..16K | BD 16K..32K (two 64x64 halves)
// ---------------------------------------------------------------------------
#define G2_STAGE 32768
#define G2_BD 16384
#define G2_SMEM (2 * G2_STAGE)

__device__ __forceinline__ void g2_load(uint32_t stg, int e, int h0, int kg,
                                        int arow0, int tid) {
#pragma unroll
    for (int it = 0; it < 4; it++) {          // A: 128 rows x 128B (padded buf)
        int idx = tid + it * 256;
        int r = idx >> 3, q = idx & 7;
        uint32_t o = SWZ((uint32_t)(r * 128 + q * 16));
        CP16(stg + o, g_hid + (size_t)(arow0 + r) * M + kg + q * 8);
    }
#pragma unroll
    for (int it = 0; it < 4; it++) {          // B: 64 k-rows x 256B (2 halves)
        int idx = tid + it * 256;
        int r = idx >> 4, q = idx & 15;
        int half = q >> 3, q7 = q & 7;
        uint32_t o = (uint32_t)(half * 8192) + SWZ((uint32_t)(r * 128 + q7 * 16));
        CP16(stg + G2_BD + o, g_wd + ((size_t)e * M + kg + r) * H + h0 + q * 8);
    }
}

__global__ void __launch_bounds__(256, 2) gemm2_mma() {
    const int e   = blockIdx.z;
    const int cnt = g_expert_count[e];
    const int t0  = blockIdx.x * 128;
    if (t0 >= cnt) return;
    const int off = g_expert_offset[e];
    const int h0  = blockIdx.y * 128;

    extern __shared__ __align__(1024) char smem[];
    const uint32_t sb = smem_u32(smem);
    const int tid = threadIdx.x, wid = tid >> 5, lane = tid & 31;
    const int warp_m = wid >> 2, warp_n = wid & 3;

    float acc[4][4][4];
#pragma unroll
    for (int a = 0; a < 4; a++)
#pragma unroll
        for (int b = 0; b < 4; b++)
#pragma unroll
            for (int c = 0; c < 4; c++) acc[a][b][c] = 0.f;

    const int nw   = warp_n * 32;
    const uint32_t bHalf = (uint32_t)((nw >> 6) * 8192);
    const int n0w  = nw & 63;

    const int NCH = M / 64;   // 56
    g2_load(sb, e, h0, 0, off + t0, tid);
    CP_COMMIT();
    for (int ch = 0; ch < NCH; ch++) {
        const uint32_t cur = sb + (uint32_t)(ch & 1) * G2_STAGE;
        if (ch + 1 < NCH) {
            g2_load(sb + (uint32_t)((ch + 1) & 1) * G2_STAGE, e, h0, (ch + 1) * 64, off + t0, tid);
            CP_COMMIT();
            CP_WAIT(1);
        } else {
            CP_WAIT(0);
        }
        __syncthreads();
        mma_chunk(acc, cur, cur + G2_BD + bHalf, warp_m * 64, n0w, lane);
        __syncthreads();
    }

    // epilogue: weighted plain stores into per-assignment partial buffer
#pragma unroll
    for (int mf = 0; mf < 4; mf++) {
        int rb = warp_m * 64 + mf * 16 + (lane >> 2);
#pragma unroll
        for (int hf = 0; hf < 2; hf++) {
            int r = rb + hf * 8;
            if (t0 + r < cnt) {
                int a = off + t0 + r;
                float w = g_assign_w[a];
                float* prow = g_part + (size_t)a * H + h0;
#pragma unroll
                for (int nf = 0; nf < 4; nf++) {
                    int c = warp_n * 32 + nf * 8 + 2 * (lane & 3);
                    prow[c]     = w * acc[mf][nf][hf * 2 + 0];
                    prow[c + 1] = w * acc[mf][nf][hf * 2 + 1];
                }
            }
        }
    }
}

// ---------------------------------------------------------------------------
// gather: out[t] = part[pos0(t)] + part[pos1(t)]
// ---------------------------------------------------------------------------
__global__ void __launch_bounds__(256) gather_kernel(float* __restrict__ out) {
    int i = blockIdx.x * 256 + threadIdx.x;      // over T*H/4
    int t  = i >> 8;                              // H/4 = 256
    int hc = i & 255;
    int p0 = g_pos_of[2 * t], p1 = g_pos_of[2 * t + 1];
    float4 v0 = ((const float4*)g_part)[(size_t)p0 * 256 + hc];
    float4 v1 = ((const float4*)g_part)[(size_t)p1 * 256 + hc];
    ((float4*)out)[i] = make_float4(v0.x + v1.x, v0.y + v1.y, v0.z + v1.z, v0.w + v1.w);
}

// ---------------------------------------------------------------------------
// launch (flat single stream)
// ---------------------------------------------------------------------------
extern "C" void kernel_launch(void* const* d_in, const int* in_sizes, int n_in,
                              void* d_out, int out_size) {
    const float* hs     = (const float*)d_in[0];
    const float* gate_w = (const float*)d_in[1];
    const float* w_gate = (const float*)d_in[2];
    const float* w_up   = (const float*)d_in[3];
    const float* w_down = (const float*)d_in[4];
    float* out = (float*)d_out;
    float* logits_out = (out_size >= T * H + T * E) ? (out + (size_t)T * H) : nullptr;

    cudaFuncSetAttribute(gemm1_mma, cudaFuncAttributeMaxDynamicSharedMemorySize, G1_SMEM);
    cudaFuncSetAttribute(gemm2_mma, cudaFuncAttributeMaxDynamicSharedMemorySize, G2_SMEM);

    xconv_kernel<<<T * H / 4 / 256, 256>>>(hs);
    const int WG3 = (int)(3 * ((size_t)E * M * H / 4) / 256);   // 86016
    convw_kernel<<<WG3, 256>>>(w_gate, w_up, w_down);

    router_kernel<<<T / 8, 256>>>(hs, gate_w, logits_out);
    build_assign_kernel<<<1, 256>>>();

    gemm1_mma<<<dim3(A_MAX / 128, M / 64, E), 256, G1_SMEM>>>();
    gemm2_mma<<<dim3(A_MAX / 128, H / 128, E), 256, G2_SMEM>>>();
    gather_kernel<<<T * H / 4 / 256, 256>>>(out);
}

// round 16
// speedup vs baseline: 1.4066x; 1.4066x over previous
#include <cuda_runtime.h>
#include <cuda_fp16.h>
#include <math.h>
#include <stdint.h>

#define H 1024
#define M 3584
#define E 8
#define T 2048
#define A_MAX (T * 2)
#define A_PAD (A_MAX + 128)   // GEMM2 A-loader reads full 128-row tiles unguarded

// ---------------------------------------------------------------------------
// scratch (device globals; allocation forbidden)
// ---------------------------------------------------------------------------
__device__ int   g_expert_count[E];
__device__ int   g_expert_offset[E];
__device__ int   g_assign_token[A_MAX];
__device__ float g_assign_w[A_MAX];
__device__ int   g_top_i[A_MAX];
__device__ float g_top_w[A_MAX];
__device__ int   g_pos_of[A_MAX];            // assignment (t*2+j) -> grouped pos

__device__ __align__(16) __half g_xh [(size_t)T * H];
__device__ __align__(16) __half g_wg [(size_t)E * H * M];   // [e][h][m] fp16
__device__ __align__(16) __half g_wu [(size_t)E * H * M];
__device__ __align__(16) __half g_wd [(size_t)E * M * H];
__device__ __align__(16) __half g_hid[(size_t)A_PAD * M];   // [pos][m], padded
__device__ __align__(16) float  g_part[(size_t)A_MAX * H];  // weighted partials

// ---------------------------------------------------------------------------
// helpers
// ---------------------------------------------------------------------------
__device__ __forceinline__ uint32_t smem_u32(const void* p) {
    uint32_t a;
    asm("{ .reg .u64 t; cvta.to.shared.u64 t, %1; cvt.u32.u64 %0, t; }" : "=r"(a) : "l"(p));
    return a;
}
#define SWZ(x) ((x) ^ (((x) >> 3) & 0x70))

#define CP16(dst, src) \
    asm volatile("cp.async.cg.shared.global [%0], [%1], 16;" \
                 :: "r"(dst), "l"(__cvta_generic_to_global(src)) : "memory")
#define CP16Z(dst, src, sz) \
    asm volatile("cp.async.cg.shared.global [%0], [%1], 16, %2;" \
                 :: "r"(dst), "l"(__cvta_generic_to_global(src)), "r"(sz) : "memory")
#define CP_COMMIT() asm volatile("cp.async.commit_group;" ::: "memory")
#define CP_WAIT(n)  asm volatile("cp.async.wait_group %0;" :: "n"(n) : "memory")

#define LDSM4(r, addr) \
    asm volatile("ldmatrix.sync.aligned.m8n8.x4.shared.b16 {%0,%1,%2,%3}, [%4];" \
        : "=r"((r)[0]), "=r"((r)[1]), "=r"((r)[2]), "=r"((r)[3]) : "r"(addr))
#define LDSM2T(r, addr) \
    asm volatile("ldmatrix.sync.aligned.m8n8.x2.trans.shared.b16 {%0,%1}, [%2];" \
        : "=r"((r)[0]), "=r"((r)[1]) : "r"(addr))

#define MMA16816(c, a, b) \
    asm volatile("mma.sync.aligned.m16n8k16.row.col.f32.f16.f16.f32 " \
        "{%0,%1,%2,%3}, {%4,%5,%6,%7}, {%8,%9}, {%0,%1,%2,%3};" \
        : "+f"((c)[0]), "+f"((c)[1]), "+f"((c)[2]), "+f"((c)[3]) \
        : "r"((a)[0]), "r"((a)[1]), "r"((a)[2]), "r"((a)[3]), "r"((b)[0]), "r"((b)[1]))

__device__ __forceinline__ uint32_t pack2h(float v0, float v1) {
    __half2 h = __floats2half2_rn(v0, v1);
    return *(uint32_t*)&h;
}

// ---------------------------------------------------------------------------
// mma core: one 64-wide K chunk, warp tile 64 rows x 32 cols (validated)
// ---------------------------------------------------------------------------
__device__ __forceinline__ void mma_chunk(float acc[4][4][4],
                                          uint32_t aP, uint32_t bP,
                                          int m0w, int n0w, int lane)
{
    const int lr = lane & 15;
    const int lc = (lane >> 4) << 3;
    const int kr = (lane & 7) + (((lane >> 3) & 1) << 3);
#pragma unroll
    for (int ks = 0; ks < 4; ks++) {
        const int k0 = ks * 16;
        uint32_t bf[4][2];
#pragma unroll
        for (int nf = 0; nf < 4; nf++) {
            int nl = n0w + nf * 8;
            uint32_t boff = SWZ((uint32_t)((k0 + kr) * 128 + nl * 2));
            LDSM2T(bf[nf], bP + boff);
        }
#pragma unroll
        for (int mf = 0; mf < 4; mf++) {
            uint32_t aoff = SWZ((uint32_t)((m0w + mf * 16 + lr) * 128 + (k0 + lc) * 2));
            uint32_t af[4];
            LDSM4(af, aP + aoff);
#pragma unroll
            for (int nf = 0; nf < 4; nf++)
                MMA16816(acc[mf][nf], af, bf[nf]);
        }
    }
}

// ---------------------------------------------------------------------------
// conversion kernels (R12-exact: 3 separate streaming launches)
// ---------------------------------------------------------------------------
__global__ void __launch_bounds__(256) convw_kernel(const float* __restrict__ in,
                                                    int which) {
    __half* outp = (which == 0) ? g_wg : (which == 1) ? g_wu : g_wd;
    size_t i = (size_t)blockIdx.x * 256 + threadIdx.x;   // over E*M*H/4
    float4 v = ((const float4*)in)[i];
    ((uint2*)outp)[i] = make_uint2(pack2h(v.x, v.y), pack2h(v.z, v.w));
}

__global__ void __launch_bounds__(256) xconv_kernel(const float* __restrict__ x) {
    size_t i = (size_t)blockIdx.x * 256 + threadIdx.x;   // over T*H/4
    float4 v = ((const float4*)x)[i];
    ((uint2*)g_xh)[i] = make_uint2(pack2h(v.x, v.y), pack2h(v.z, v.w));
}

// ---------------------------------------------------------------------------
// router (R12-exact: block-per-token)
// ---------------------------------------------------------------------------
__global__ void __launch_bounds__(128) router_kernel(
    const float* __restrict__ x, const float* __restrict__ gw,
    float* __restrict__ logits_out)
{
    const int t = blockIdx.x;
    const int tid = threadIdx.x;
    const float* xr = x + (size_t)t * H;
    float acc[E];
#pragma unroll
    for (int e = 0; e < E; e++) acc[e] = 0.f;
    for (int h = tid; h < H; h += 128) {
        float xv = xr[h];
        const float* g = gw + (size_t)h * E;
#pragma unroll
        for (int e = 0; e < E; e++) acc[e] += xv * g[e];
    }
    __shared__ float red[128][E];
#pragma unroll
    for (int e = 0; e < E; e++) red[tid][e] = acc[e];
    __syncthreads();
    for (int s = 64; s > 0; s >>= 1) {
        if (tid < s)
#pragma unroll
            for (int e = 0; e < E; e++) red[tid][e] += red[tid + s][e];
        __syncthreads();
    }
    if (tid == 0) {
        float l[E];
#pragma unroll
        for (int e = 0; e < E; e++) {
            l[e] = red[0][e];
            if (logits_out) logits_out[(size_t)t * E + e] = l[e];
        }
        float mx = l[0];
#pragma unroll
        for (int e = 1; e < E; e++) mx = fmaxf(mx, l[e]);
        float p[E];
#pragma unroll
        for (int e = 0; e < E; e++) p[e] = expf(l[e] - mx);
        int i0 = 0;
#pragma unroll
        for (int e = 1; e < E; e++) if (p[e] > p[i0]) i0 = e;
        int i1 = (i0 == 0) ? 1 : 0;
#pragma unroll
        for (int e = 0; e < E; e++) if (e != i0 && p[e] > p[i1]) i1 = e;
        float s2 = p[i0] + p[i1];
        g_top_i[t * 2 + 0] = i0; g_top_w[t * 2 + 0] = p[i0] / s2;
        g_top_i[t * 2 + 1] = i1; g_top_w[t * 2 + 1] = p[i1] / s2;
    }
}

// ---------------------------------------------------------------------------
// build_assign: 1024 threads + match_any warp-aggregated atomics
// (positions permute vs R12, but all consumers are position-independent)
// ---------------------------------------------------------------------------
__global__ void __launch_bounds__(1024) build_assign_kernel() {
    __shared__ int cnt[E], cur[E];
    const int tid = threadIdx.x;
    const int lane = tid & 31;
    if (tid < E) cnt[tid] = 0;
    __syncthreads();

    // pass 1: count (one atomic per warp-expert group)
#pragma unroll
    for (int it = 0; it < A_MAX / 1024; it++) {
        int a = tid + it * 1024;
        int e = g_top_i[a];
        unsigned mask = __match_any_sync(0xffffffffu, e);
        if ((int)(__ffs(mask) - 1) == lane)
            atomicAdd(&cnt[e], __popc(mask));
    }
    __syncthreads();
    if (tid == 0) {
        int o = 0;
        for (int e = 0; e < E; e++) {
            g_expert_count[e] = cnt[e];
            g_expert_offset[e] = o;
            cur[e] = o;
            o += cnt[e];
        }
    }
    __syncthreads();

    // pass 2: scatter (one atomic per warp-expert group; rank via popc)
#pragma unroll
    for (int it = 0; it < A_MAX / 1024; it++) {
        int a = tid + it * 1024;
        int e = g_top_i[a];
        unsigned mask = __match_any_sync(0xffffffffu, e);
        int leader = (int)(__ffs(mask) - 1);
        int rank = __popc(mask & ((1u << lane) - 1u));
        int base = 0;
        if (lane == leader) base = atomicAdd(&cur[e], __popc(mask));
        base = __shfl_sync(0xffffffffu, base, leader);
        int pos = base + rank;
        g_assign_token[pos] = a >> 1;
        g_assign_w[pos]     = g_top_w[a];
        g_pos_of[a]         = pos;
    }
}

// ---------------------------------------------------------------------------
// GEMM1 (R12-exact): hidden = silu(X*Wg) * (X*Wu)
// 128 gathered rows x 64 cols; warps 0-3 gate, 4-7 up; 2-stage cp.async
// stage (32KB): A 0..16K | BG 16K..24K | BU 24K..32K
// ---------------------------------------------------------------------------
#define G1_STAGE 32768
#define G1_BG 16384
#define G1_BU 24576
#define G1_SROW (2 * G1_STAGE)
#define G1_SMEM (2 * G1_STAGE + 512)

__device__ __forceinline__ void g1_load(uint32_t stg, int e, int n0, int kg,
                                        const int* srow, int tid) {
#pragma unroll
    for (int it = 0; it < 4; it++) {          // A: 128 rows x 128B
        int idx = tid + it * 256;
        int r = idx >> 3, q = idx & 7;
        int tok = srow[r];
        uint32_t sz = (tok >= 0) ? 16u : 0u;
        int tk = (tok >= 0) ? tok : 0;
        uint32_t o = SWZ((uint32_t)(r * 128 + q * 16));
        CP16Z(stg + o, g_xh + (size_t)tk * H + kg + q * 8, sz);
    }
#pragma unroll
    for (int it = 0; it < 2; it++) {          // Bg, Bu: rows = k (h), cols = n (m)
        int idx = tid + it * 256;
        int r = idx >> 3, q = idx & 7;
        size_t go = ((size_t)e * H + kg + r) * M + n0 + q * 8;
        uint32_t o = SWZ((uint32_t)(r * 128 + q * 16));
        CP16(stg + G1_BG + o, g_wg + go);
        CP16(stg + G1_BU + o, g_wu + go);
    }
}

__global__ void __launch_bounds__(256, 2) gemm1_mma() {
    const int e   = blockIdx.z;
    const int cnt = g_expert_count[e];
    const int t0  = blockIdx.x * 128;
    if (t0 >= cnt) return;
    const int off = g_expert_offset[e];
    const int n0  = blockIdx.y * 64;

    extern __shared__ __align__(1024) char smem[];
    const uint32_t sb = smem_u32(smem);
    int* srow = (int*)(smem + G1_SROW);
    const int tid = threadIdx.x, wid = tid >> 5, lane = tid & 31;

    if (tid < 128)
        srow[tid] = (t0 + tid < cnt) ? g_assign_token[off + t0 + tid] : -1;
    __syncthreads();

    const int gwp    = wid & 3;
    const int warp_m = gwp >> 1, warp_n = gwp & 1;
    const bool isUp  = wid >= 4;

    float acc[4][4][4];
#pragma unroll
    for (int a = 0; a < 4; a++)
#pragma unroll
        for (int b = 0; b < 4; b++)
#pragma unroll
            for (int c = 0; c < 4; c++) acc[a][b][c] = 0.f;

    const uint32_t bOff = isUp ? G1_BU : G1_BG;

    const int NCH = H / 64;   // 16
    g1_load(sb, e, n0, 0, srow, tid);
    CP_COMMIT();
    for (int ch = 0; ch < NCH; ch++) {
        const uint32_t cur = sb + (uint32_t)(ch & 1) * G1_STAGE;
        if (ch + 1 < NCH) {
            g1_load(sb + (uint32_t)((ch + 1) & 1) * G1_STAGE, e, n0, (ch + 1) * 64, srow, tid);
            CP_COMMIT();
            CP_WAIT(1);
        } else {
            CP_WAIT(0);
        }
        __syncthreads();
        mma_chunk(acc, cur, cur + bOff, warp_m * 64, warp_n * 32, lane);
        __syncthreads();
    }

    // epilogue: exchange up accums via smem, gate warps compute + store fp16
    float* smemU = (float*)smem;   // [128][65] fp32 overlay
    if (isUp) {
#pragma unroll
        for (int mf = 0; mf < 4; mf++)
#pragma unroll
            for (int nf = 0; nf < 4; nf++)
#pragma unroll
                for (int i = 0; i < 4; i++) {
                    int r = warp_m * 64 + mf * 16 + (lane >> 2) + ((i >> 1) << 3);
                    int c = warp_n * 32 + nf * 8 + 2 * (lane & 3) + (i & 1);
                    smemU[r * 65 + c] = acc[mf][nf][i];
                }
    }
    __syncthreads();
    if (!isUp) {
#pragma unroll
        for (int mf = 0; mf < 4; mf++)
#pragma unroll
            for (int nf = 0; nf < 4; nf++) {
                int rb = warp_m * 64 + mf * 16 + (lane >> 2);
                int cb = warp_n * 32 + nf * 8 + 2 * (lane & 3);
#pragma unroll
                for (int hf = 0; hf < 2; hf++) {
                    int r = rb + hf * 8;
                    if (t0 + r < cnt) {
                        float g0 = acc[mf][nf][hf * 2 + 0];
                        float g1 = acc[mf][nf][hf * 2 + 1];
                        float u0 = smemU[r * 65 + cb];
                        float u1 = smemU[r * 65 + cb + 1];
                        float h0 = (g0 / (1.f + __expf(-g0))) * u0;
                        float h1 = (g1 / (1.f + __expf(-g1))) * u1;
                        *(uint32_t*)(g_hid + (size_t)(off + t0 + r) * M + n0 + cb)
                            = pack2h(h0, h1);
                    }
                }
            }
    }
}

// ---------------------------------------------------------------------------
// GEMM2 (R12-exact): part[pos] = w * (hidden * Wd)
// 128 rows x 128 H-cols; 8 warps (2m x 4n); 2-stage cp.async
// stage (32KB): A 0..16K | BD 16K..32K (two 64x64 halves)
// ---------------------------------------------------------------------------
#define G2_STAGE 32768
#define G2_BD 16384
#define G2_SMEM (2 * G2_STAGE)

__device__ __forceinline__ void g2_load(uint32_t stg, int e, int h0, int kg,
                                        int arow0, int tid) {
#pragma unroll
    for (int it = 0; it < 4; it++) {          // A: 128 rows x 128B (padded buf)
        int idx = tid + it * 256;
        int r = idx >> 3, q = idx & 7;
        uint32_t o = SWZ((uint32_t)(r * 128 + q * 16));
        CP16(stg + o, g_hid + (size_t)(arow0 + r) * M + kg + q * 8);
    }
#pragma unroll
    for (int it = 0; it < 4; it++) {          // B: 64 k-rows x 256B (2 halves)
        int idx = tid + it * 256;
        int r = idx >> 4, q = idx & 15;
        int half = q >> 3, q7 = q & 7;
        uint32_t o = (uint32_t)(half * 8192) + SWZ((uint32_t)(r * 128 + q7 * 16));
        CP16(stg + G2_BD + o, g_wd + ((size_t)e * M + kg + r) * H + h0 + q * 8);
    }
}

__global__ void __launch_bounds__(256, 2) gemm2_mma() {
    const int e   = blockIdx.z;
    const int cnt = g_expert_count[e];
    const int t0  = blockIdx.x * 128;
    if (t0 >= cnt) return;
    const int off = g_expert_offset[e];
    const int h0  = blockIdx.y * 128;

    extern __shared__ __align__(1024) char smem[];
    const uint32_t sb = smem_u32(smem);
    const int tid = threadIdx.x, wid = tid >> 5, lane = tid & 31;
    const int warp_m = wid >> 2, warp_n = wid & 3;

    float acc[4][4][4];
#pragma unroll
    for (int a = 0; a < 4; a++)
#pragma unroll
        for (int b = 0; b < 4; b++)
#pragma unroll
            for (int c = 0; c < 4; c++) acc[a][b][c] = 0.f;

    const int nw   = warp_n * 32;
    const uint32_t bHalf = (uint32_t)((nw >> 6) * 8192);
    const int n0w  = nw & 63;

    const int NCH = M / 64;   // 56
    g2_load(sb, e, h0, 0, off + t0, tid);
    CP_COMMIT();
    for (int ch = 0; ch < NCH; ch++) {
        const uint32_t cur = sb + (uint32_t)(ch & 1) * G2_STAGE;
        if (ch + 1 < NCH) {
            g2_load(sb + (uint32_t)((ch + 1) & 1) * G2_STAGE, e, h0, (ch + 1) * 64, off + t0, tid);
            CP_COMMIT();
            CP_WAIT(1);
        } else {
            CP_WAIT(0);
        }
        __syncthreads();
        mma_chunk(acc, cur, cur + G2_BD + bHalf, warp_m * 64, n0w, lane);
        __syncthreads();
    }

    // epilogue: weighted plain stores into per-assignment partial buffer
#pragma unroll
    for (int mf = 0; mf < 4; mf++) {
        int rb = warp_m * 64 + mf * 16 + (lane >> 2);
#pragma unroll
        for (int hf = 0; hf < 2; hf++) {
            int r = rb + hf * 8;
            if (t0 + r < cnt) {
                int a = off + t0 + r;
                float w = g_assign_w[a];
                float* prow = g_part + (size_t)a * H + h0;
#pragma unroll
                for (int nf = 0; nf < 4; nf++) {
                    int c = warp_n * 32 + nf * 8 + 2 * (lane & 3);
                    prow[c]     = w * acc[mf][nf][hf * 2 + 0];
                    prow[c + 1] = w * acc[mf][nf][hf * 2 + 1];
                }
            }
        }
    }
}

// ---------------------------------------------------------------------------
// gather: out[t] = part[pos0(t)] + part[pos1(t)]
// ---------------------------------------------------------------------------
__global__ void __launch_bounds__(256) gather_kernel(float* __restrict__ out) {
    int i = blockIdx.x * 256 + threadIdx.x;      // over T*H/4
    int t  = i >> 8;                              // H/4 = 256
    int hc = i & 255;
    int p0 = g_pos_of[2 * t], p1 = g_pos_of[2 * t + 1];
    float4 v0 = ((const float4*)g_part)[(size_t)p0 * 256 + hc];
    float4 v1 = ((const float4*)g_part)[(size_t)p1 * 256 + hc];
    ((float4*)out)[i] = make_float4(v0.x + v1.x, v0.y + v1.y, v0.z + v1.z, v0.w + v1.w);
}

// ---------------------------------------------------------------------------
// launch (flat single stream, R12-exact ordering)
// ---------------------------------------------------------------------------
extern "C" void kernel_launch(void* const* d_in, const int* in_sizes, int n_in,
                              void* d_out, int out_size) {
    const float* hs     = (const float*)d_in[0];
    const float* gate_w = (const float*)d_in[1];
    const float* w_gate = (const float*)d_in[2];
    const float* w_up   = (const float*)d_in[3];
    const float* w_down = (const float*)d_in[4];
    float* out = (float*)d_out;
    float* logits_out = (out_size >= T * H + T * E) ? (out + (size_t)T * H) : nullptr;

    cudaFuncSetAttribute(gemm1_mma, cudaFuncAttributeMaxDynamicSharedMemorySize, G1_SMEM);
    cudaFuncSetAttribute(gemm2_mma, cudaFuncAttributeMaxDynamicSharedMemorySize, G2_SMEM);

    xconv_kernel<<<T * H / 4 / 256, 256>>>(hs);
    const int WG = (int)((size_t)E * M * H / 4 / 256);   // 28672
    convw_kernel<<<WG, 256>>>(w_gate, 0);
    convw_kernel<<<WG, 256>>>(w_up,   1);
    convw_kernel<<<WG, 256>>>(w_down, 2);

    router_kernel<<<T, 128>>>(hs, gate_w, logits_out);
    build_assign_kernel<<<1, 1024>>>();

    gemm1_mma<<<dim3(A_MAX / 128, M / 64, E), 256, G1_SMEM>>>();
    gemm2_mma<<<dim3(A_MAX / 128, H / 128, E), 256, G2_SMEM>>>();
    gather_kernel<<<T * H / 4 / 256, 256>>>(out);
}

// round 17
// speedup vs baseline: 1.4405x; 1.0241x over previous
#include <cuda_runtime.h>
#include <cuda_fp16.h>
#include <math.h>
#include <stdint.h>

#define H 1024
#define M 3584
#define E 8
#define T 2048
#define A_MAX (T * 2)
#define A_PAD (A_MAX + 128)   // GEMM2 A-loader reads full 128-row tiles unguarded

// ---------------------------------------------------------------------------
// scratch (device globals; allocation forbidden)
// ---------------------------------------------------------------------------
__device__ int   g_expert_count[E];
__device__ int   g_expert_offset[E];
__device__ int   g_assign_token[A_MAX];
__device__ float g_assign_w[A_MAX];
__device__ int   g_top_i[A_MAX];
__device__ float g_top_w[A_MAX];
__device__ int   g_pos_of[A_MAX];            // assignment (t*2+j) -> grouped pos

__device__ __align__(16) __half g_xh [(size_t)T * H];
__device__ __align__(16) __half g_wg [(size_t)E * H * M];   // [e][h][m] fp16
__device__ __align__(16) __half g_wu [(size_t)E * H * M];
__device__ __align__(16) __half g_wd [(size_t)E * M * H];
__device__ __align__(16) __half g_hid[(size_t)A_PAD * M];   // [pos][m], padded
__device__ __align__(16) float  g_part[(size_t)A_MAX * H];  // weighted partials

// ---------------------------------------------------------------------------
// helpers
// ---------------------------------------------------------------------------
__device__ __forceinline__ uint32_t smem_u32(const void* p) {
    uint32_t a;
    asm("{ .reg .u64 t; cvta.to.shared.u64 t, %1; cvt.u32.u64 %0, t; }" : "=r"(a) : "l"(p));
    return a;
}
#define SWZ(x) ((x) ^ (((x) >> 3) & 0x70))

#define CP16(dst, src) \
    asm volatile("cp.async.cg.shared.global [%0], [%1], 16;" \
                 :: "r"(dst), "l"(__cvta_generic_to_global(src)) : "memory")
#define CP16Z(dst, src, sz) \
    asm volatile("cp.async.cg.shared.global [%0], [%1], 16, %2;" \
                 :: "r"(dst), "l"(__cvta_generic_to_global(src)), "r"(sz) : "memory")
#define CP_COMMIT() asm volatile("cp.async.commit_group;" ::: "memory")
#define CP_WAIT(n)  asm volatile("cp.async.wait_group %0;" :: "n"(n) : "memory")

#define LDSM4(r, addr) \
    asm volatile("ldmatrix.sync.aligned.m8n8.x4.shared.b16 {%0,%1,%2,%3}, [%4];" \
        : "=r"((r)[0]), "=r"((r)[1]), "=r"((r)[2]), "=r"((r)[3]) : "r"(addr))
#define LDSM2T(r, addr) \
    asm volatile("ldmatrix.sync.aligned.m8n8.x2.trans.shared.b16 {%0,%1}, [%2];" \
        : "=r"((r)[0]), "=r"((r)[1]) : "r"(addr))

#define MMA16816(c, a, b) \
    asm volatile("mma.sync.aligned.m16n8k16.row.col.f32.f16.f16.f32 " \
        "{%0,%1,%2,%3}, {%4,%5,%6,%7}, {%8,%9}, {%0,%1,%2,%3};" \
        : "+f"((c)[0]), "+f"((c)[1]), "+f"((c)[2]), "+f"((c)[3]) \
        : "r"((a)[0]), "r"((a)[1]), "r"((a)[2]), "r"((a)[3]), "r"((b)[0]), "r"((b)[1]))

__device__ __forceinline__ uint32_t pack2h(float v0, float v1) {
    __half2 h = __floats2half2_rn(v0, v1);
    return *(uint32_t*)&h;
}

// ---------------------------------------------------------------------------
// mma core: one 64-wide K chunk, warp tile 64 rows x 32 cols (validated)
// ---------------------------------------------------------------------------
__device__ __forceinline__ void mma_chunk(float acc[4][4][4],
                                          uint32_t aP, uint32_t bP,
                                          int m0w, int n0w, int lane)
{
    const int lr = lane & 15;
    const int lc = (lane >> 4) << 3;
    const int kr = (lane & 7) + (((lane >> 3) & 1) << 3);
#pragma unroll
    for (int ks = 0; ks < 4; ks++) {
        const int k0 = ks * 16;
        uint32_t bf[4][2];
#pragma unroll
        for (int nf = 0; nf < 4; nf++) {
            int nl = n0w + nf * 8;
            uint32_t boff = SWZ((uint32_t)((k0 + kr) * 128 + nl * 2));
            LDSM2T(bf[nf], bP + boff);
        }
#pragma unroll
        for (int mf = 0; mf < 4; mf++) {
            uint32_t aoff = SWZ((uint32_t)((m0w + mf * 16 + lr) * 128 + (k0 + lc) * 2));
            uint32_t af[4];
            LDSM4(af, aP + aoff);
#pragma unroll
            for (int nf = 0; nf < 4; nf++)
                MMA16816(acc[mf][nf], af, bf[nf]);
        }
    }
}

// ---------------------------------------------------------------------------
// conversion kernels: MLP=4 per thread, evict-first reads
// block covers 1024 consecutive float4s (4 per thread spaced 256)
// ---------------------------------------------------------------------------
__global__ void __launch_bounds__(256) convw_kernel(const float* __restrict__ in,
                                                    int which) {
    __half* outp = (which == 0) ? g_wg : (which == 1) ? g_wu : g_wd;
    size_t base = (size_t)blockIdx.x * 1024 + threadIdx.x;
    const float4* in4 = (const float4*)in;
    uint2* out2 = (uint2*)outp;
    float4 v[4];
#pragma unroll
    for (int j = 0; j < 4; j++) v[j] = __ldcs(in4 + base + j * 256);
#pragma unroll
    for (int j = 0; j < 4; j++)
        out2[base + j * 256] = make_uint2(pack2h(v[j].x, v[j].y),
                                          pack2h(v[j].z, v[j].w));
}

__global__ void __launch_bounds__(256) xconv_kernel(const float* __restrict__ x) {
    size_t base = (size_t)blockIdx.x * 1024 + threadIdx.x;   // over T*H/4
    const float4* in4 = (const float4*)x;
    uint2* out2 = (uint2*)g_xh;
    float4 v[4];
#pragma unroll
    for (int j = 0; j < 4; j++) v[j] = __ldcs(in4 + base + j * 256);
#pragma unroll
    for (int j = 0; j < 4; j++)
        out2[base + j * 256] = make_uint2(pack2h(v[j].x, v[j].y),
                                          pack2h(v[j].z, v[j].w));
}

// ---------------------------------------------------------------------------
// router (validated block-per-token)
// ---------------------------------------------------------------------------
__global__ void __launch_bounds__(128) router_kernel(
    const float* __restrict__ x, const float* __restrict__ gw,
    float* __restrict__ logits_out)
{
    const int t = blockIdx.x;
    const int tid = threadIdx.x;
    const float* xr = x + (size_t)t * H;
    float acc[E];
#pragma unroll
    for (int e = 0; e < E; e++) acc[e] = 0.f;
    for (int h = tid; h < H; h += 128) {
        float xv = xr[h];
        const float* g = gw + (size_t)h * E;
#pragma unroll
        for (int e = 0; e < E; e++) acc[e] += xv * g[e];
    }
    __shared__ float red[128][E];
#pragma unroll
    for (int e = 0; e < E; e++) red[tid][e] = acc[e];
    __syncthreads();
    for (int s = 64; s > 0; s >>= 1) {
        if (tid < s)
#pragma unroll
            for (int e = 0; e < E; e++) red[tid][e] += red[tid + s][e];
        __syncthreads();
    }
    if (tid == 0) {
        float l[E];
#pragma unroll
        for (int e = 0; e < E; e++) {
            l[e] = red[0][e];
            if (logits_out) logits_out[(size_t)t * E + e] = l[e];
        }
        float mx = l[0];
#pragma unroll
        for (int e = 1; e < E; e++) mx = fmaxf(mx, l[e]);
        float p[E];
#pragma unroll
        for (int e = 0; e < E; e++) p[e] = expf(l[e] - mx);
        int i0 = 0;
#pragma unroll
        for (int e = 1; e < E; e++) if (p[e] > p[i0]) i0 = e;
        int i1 = (i0 == 0) ? 1 : 0;
#pragma unroll
        for (int e = 0; e < E; e++) if (e != i0 && p[e] > p[i1]) i1 = e;
        float s2 = p[i0] + p[i1];
        g_top_i[t * 2 + 0] = i0; g_top_w[t * 2 + 0] = p[i0] / s2;
        g_top_i[t * 2 + 1] = i1; g_top_w[t * 2 + 1] = p[i1] / s2;
    }
}

// ---------------------------------------------------------------------------
// build_assign (R15-validated: match_any warp-aggregated atomics)
// ---------------------------------------------------------------------------
__global__ void __launch_bounds__(1024) build_assign_kernel() {
    __shared__ int cnt[E], cur[E];
    const int tid = threadIdx.x;
    const int lane = tid & 31;
    if (tid < E) cnt[tid] = 0;
    __syncthreads();

#pragma unroll
    for (int it = 0; it < A_MAX / 1024; it++) {
        int a = tid + it * 1024;
        int e = g_top_i[a];
        unsigned mask = __match_any_sync(0xffffffffu, e);
        if ((int)(__ffs(mask) - 1) == lane)
            atomicAdd(&cnt[e], __popc(mask));
    }
    __syncthreads();
    if (tid == 0) {
        int o = 0;
        for (int e = 0; e < E; e++) {
            g_expert_count[e] = cnt[e];
            g_expert_offset[e] = o;
            cur[e] = o;
            o += cnt[e];
        }
    }
    __syncthreads();

#pragma unroll
    for (int it = 0; it < A_MAX / 1024; it++) {
        int a = tid + it * 1024;
        int e = g_top_i[a];
        unsigned mask = __match_any_sync(0xffffffffu, e);
        int leader = (int)(__ffs(mask) - 1);
        int rank = __popc(mask & ((1u << lane) - 1u));
        int base = 0;
        if (lane == leader) base = atomicAdd(&cur[e], __popc(mask));
        base = __shfl_sync(0xffffffffu, base, leader);
        int pos = base + rank;
        g_assign_token[pos] = a >> 1;
        g_assign_w[pos]     = g_top_w[a];
        g_pos_of[a]         = pos;
    }
}

// ---------------------------------------------------------------------------
// GEMM1 (R12-exact): hidden = silu(X*Wg) * (X*Wu)
// 128 gathered rows x 64 cols; warps 0-3 gate, 4-7 up; 2-stage cp.async
// stage (32KB): A 0..16K | BG 16K..24K | BU 24K..32K
// ---------------------------------------------------------------------------
#define G1_STAGE 32768
#define G1_BG 16384
#define G1_BU 24576
#define G1_SROW (2 * G1_STAGE)
#define G1_SMEM (2 * G1_STAGE + 512)

__device__ __forceinline__ void g1_load(uint32_t stg, int e, int n0, int kg,
                                        const int* srow, int tid) {
#pragma unroll
    for (int it = 0; it < 4; it++) {          // A: 128 rows x 128B
        int idx = tid + it * 256;
        int r = idx >> 3, q = idx & 7;
        int tok = srow[r];
        uint32_t sz = (tok >= 0) ? 16u : 0u;
        int tk = (tok >= 0) ? tok : 0;
        uint32_t o = SWZ((uint32_t)(r * 128 + q * 16));
        CP16Z(stg + o, g_xh + (size_t)tk * H + kg + q * 8, sz);
    }
#pragma unroll
    for (int it = 0; it < 2; it++) {          // Bg, Bu: rows = k (h), cols = n (m)
        int idx = tid + it * 256;
        int r = idx >> 3, q = idx & 7;
        size_t go = ((size_t)e * H + kg + r) * M + n0 + q * 8;
        uint32_t o = SWZ((uint32_t)(r * 128 + q * 16));
        CP16(stg + G1_BG + o, g_wg + go);
        CP16(stg + G1_BU + o, g_wu + go);
    }
}

__global__ void __launch_bounds__(256, 2) gemm1_mma() {
    const int e   = blockIdx.z;
    const int cnt = g_expert_count[e];
    const int t0  = blockIdx.x * 128;
    if (t0 >= cnt) return;
    const int off = g_expert_offset[e];
    const int n0  = blockIdx.y * 64;

    extern __shared__ __align__(1024) char smem[];
    const uint32_t sb = smem_u32(smem);
    int* srow = (int*)(smem + G1_SROW);
    const int tid = threadIdx.x, wid = tid >> 5, lane = tid & 31;

    if (tid < 128)
        srow[tid] = (t0 + tid < cnt) ? g_assign_token[off + t0 + tid] : -1;
    __syncthreads();

    const int gwp    = wid & 3;
    const int warp_m = gwp >> 1, warp_n = gwp & 1;
    const bool isUp  = wid >= 4;

    float acc[4][4][4];
#pragma unroll
    for (int a = 0; a < 4; a++)
#pragma unroll
        for (int b = 0; b < 4; b++)
#pragma unroll
            for (int c = 0; c < 4; c++) acc[a][b][c] = 0.f;

    const uint32_t bOff = isUp ? G1_BU : G1_BG;

    const int NCH = H / 64;   // 16
    g1_load(sb, e, n0, 0, srow, tid);
    CP_COMMIT();
    for (int ch = 0; ch < NCH; ch++) {
        const uint32_t cur = sb + (uint32_t)(ch & 1) * G1_STAGE;
        if (ch + 1 < NCH) {
            g1_load(sb + (uint32_t)((ch + 1) & 1) * G1_STAGE, e, n0, (ch + 1) * 64, srow, tid);
            CP_COMMIT();
            CP_WAIT(1);
        } else {
            CP_WAIT(0);
        }
        __syncthreads();
        mma_chunk(acc, cur, cur + bOff, warp_m * 64, warp_n * 32, lane);
        __syncthreads();
    }

    // epilogue: exchange up accums via smem, gate warps compute + store fp16
    float* smemU = (float*)smem;   // [128][65] fp32 overlay
    if (isUp) {
#pragma unroll
        for (int mf = 0; mf < 4; mf++)
#pragma unroll
            for (int nf = 0; nf < 4; nf++)
#pragma unroll
                for (int i = 0; i < 4; i++) {
                    int r = warp_m * 64 + mf * 16 + (lane >> 2) + ((i >> 1) << 3);
                    int c = warp_n * 32 + nf * 8 + 2 * (lane & 3) + (i & 1);
                    smemU[r * 65 + c] = acc[mf][nf][i];
                }
    }
    __syncthreads();
    if (!isUp) {
#pragma unroll
        for (int mf = 0; mf < 4; mf++)
#pragma unroll
            for (int nf = 0; nf < 4; nf++) {
                int rb = warp_m * 64 + mf * 16 + (lane >> 2);
                int cb = warp_n * 32 + nf * 8 + 2 * (lane & 3);
#pragma unroll
                for (int hf = 0; hf < 2; hf++) {
                    int r = rb + hf * 8;
                    if (t0 + r < cnt) {
                        float g0 = acc[mf][nf][hf * 2 + 0];
                        float g1 = acc[mf][nf][hf * 2 + 1];
                        float u0 = smemU[r * 65 + cb];
                        float u1 = smemU[r * 65 + cb + 1];
                        float h0 = (g0 / (1.f + __expf(-g0))) * u0;
                        float h1 = (g1 / (1.f + __expf(-g1))) * u1;
                        *(uint32_t*)(g_hid + (size_t)(off + t0 + r) * M + n0 + cb)
                            = pack2h(h0, h1);
                    }
                }
            }
    }
}

// ---------------------------------------------------------------------------
// GEMM2 (R12-exact): part[pos] = w * (hidden * Wd)
// 128 rows x 128 H-cols; 8 warps (2m x 4n); 2-stage cp.async
// stage (32KB): A 0..16K | BD 16K..32K (two 64x64 halves)
// ---------------------------------------------------------------------------
#define G2_STAGE 32768
#define G2_BD 16384
#define G2_SMEM (2 * G2_STAGE)

__device__ __forceinline__ void g2_load(uint32_t stg, int e, int h0, int kg,
                                        int arow0, int tid) {
#pragma unroll
    for (int it = 0; it < 4; it++) {          // A: 128 rows x 128B (padded buf)
        int idx = tid + it * 256;
        int r = idx >> 3, q = idx & 7;
        uint32_t o = SWZ((uint32_t)(r * 128 + q * 16));
        CP16(stg + o, g_hid + (size_t)(arow0 + r) * M + kg + q * 8);
    }
#pragma unroll
    for (int it = 0; it < 4; it++) {          // B: 64 k-rows x 256B (2 halves)
        int idx = tid + it * 256;
        int r = idx >> 4, q = idx & 15;
        int half = q >> 3, q7 = q & 7;
        uint32_t o = (uint32_t)(half * 8192) + SWZ((uint32_t)(r * 128 + q7 * 16));
        CP16(stg + G2_BD + o, g_wd + ((size_t)e * M + kg + r) * H + h0 + q * 8);
    }
}

__global__ void __launch_bounds__(256, 2) gemm2_mma() {
    const int e   = blockIdx.z;
    const int cnt = g_expert_count[e];
    const int t0  = blockIdx.x * 128;
    if (t0 >= cnt) return;
    const int off = g_expert_offset[e];
    const int h0  = blockIdx.y * 128;

    extern __shared__ __align__(1024) char smem[];
    const uint32_t sb = smem_u32(smem);
    const int tid = threadIdx.x, wid = tid >> 5, lane = tid & 31;
    const int warp_m = wid >> 2, warp_n = wid & 3;

    float acc[4][4][4];
#pragma unroll
    for (int a = 0; a < 4; a++)
#pragma unroll
        for (int b = 0; b < 4; b++)
#pragma unroll
            for (int c = 0; c < 4; c++) acc[a][b][c] = 0.f;

    const int nw   = warp_n * 32;
    const uint32_t bHalf = (uint32_t)((nw >> 6) * 8192);
    const int n0w  = nw & 63;

    const int NCH = M / 64;   // 56
    g2_load(sb, e, h0, 0, off + t0, tid);
    CP_COMMIT();
    for (int ch = 0; ch < NCH; ch++) {
        const uint32_t cur = sb + (uint32_t)(ch & 1) * G2_STAGE;
        if (ch + 1 < NCH) {
            g2_load(sb + (uint32_t)((ch + 1) & 1) * G2_STAGE, e, h0, (ch + 1) * 64, off + t0, tid);
            CP_COMMIT();
            CP_WAIT(1);
        } else {
            CP_WAIT(0);
        }
        __syncthreads();
        mma_chunk(acc, cur, cur + G2_BD + bHalf, warp_m * 64, n0w, lane);
        __syncthreads();
    }

    // epilogue: weighted plain stores into per-assignment partial buffer
#pragma unroll
    for (int mf = 0; mf < 4; mf++) {
        int rb = warp_m * 64 + mf * 16 + (lane >> 2);
#pragma unroll
        for (int hf = 0; hf < 2; hf++) {
            int r = rb + hf * 8;
            if (t0 + r < cnt) {
                int a = off + t0 + r;
                float w = g_assign_w[a];
                float* prow = g_part + (size_t)a * H + h0;
#pragma unroll
                for (int nf = 0; nf < 4; nf++) {
                    int c = warp_n * 32 + nf * 8 + 2 * (lane & 3);
                    prow[c]     = w * acc[mf][nf][hf * 2 + 0];
                    prow[c + 1] = w * acc[mf][nf][hf * 2 + 1];
                }
            }
        }
    }
}

// ---------------------------------------------------------------------------
// gather: out[t] = part[pos0(t)] + part[pos1(t)]
// ---------------------------------------------------------------------------
__global__ void __launch_bounds__(256) gather_kernel(float* __restrict__ out) {
    int i = blockIdx.x * 256 + threadIdx.x;      // over T*H/4
    int t  = i >> 8;                              // H/4 = 256
    int hc = i & 255;
    int p0 = g_pos_of[2 * t], p1 = g_pos_of[2 * t + 1];
    float4 v0 = ((const float4*)g_part)[(size_t)p0 * 256 + hc];
    float4 v1 = ((const float4*)g_part)[(size_t)p1 * 256 + hc];
    ((float4*)out)[i] = make_float4(v0.x + v1.x, v0.y + v1.y, v0.z + v1.z, v0.w + v1.w);
}

// ---------------------------------------------------------------------------
// launch (flat single stream)
// ---------------------------------------------------------------------------
extern "C" void kernel_launch(void* const* d_in, const int* in_sizes, int n_in,
                              void* d_out, int out_size) {
    const float* hs     = (const float*)d_in[0];
    const float* gate_w = (const float*)d_in[1];
    const float* w_gate = (const float*)d_in[2];
    const float* w_up   = (const float*)d_in[3];
    const float* w_down = (const float*)d_in[4];
    float* out = (float*)d_out;
    float* logits_out = (out_size >= T * H + T * E) ? (out + (size_t)T * H) : nullptr;

    cudaFuncSetAttribute(gemm1_mma, cudaFuncAttributeMaxDynamicSharedMemorySize, G1_SMEM);
    cudaFuncSetAttribute(gemm2_mma, cudaFuncAttributeMaxDynamicSharedMemorySize, G2_SMEM);

    xconv_kernel<<<T * H / 4 / 1024, 256>>>(hs);              // 512 blocks
    const int WG = (int)((size_t)E * M * H / 4 / 1024);       // 7168 blocks
    convw_kernel<<<WG, 256>>>(w_gate, 0);
    convw_kernel<<<WG, 256>>>(w_up,   1);
    convw_kernel<<<WG, 256>>>(w_down, 2);

    router_kernel<<<T, 128>>>(hs, gate_w, logits_out);
    build_assign_kernel<<<1, 1024>>>();

    gemm1_mma<<<dim3(A_MAX / 128, M / 64, E), 256, G1_SMEM>>>();
    gemm2_mma<<<dim3(A_MAX / 128, H / 128, E), 256, G2_SMEM>>>();
    gather_kernel<<<T * H / 4 / 1024 * 4, 256>>>(out);
}